// round 5
// baseline (speedup 1.0000x reference)
#include <cuda_runtime.h>
#include <cstdint>

#define B    256
#define T    1024
#define H    256
#define INP  32
#define OUTD 32
#define G3   768
#define NC   128   // persistent CTAs (all resident)
#define THR  512

typedef unsigned long long u64;

// Static device scratch (allocation-free rule)
__device__ float g_obsT[(size_t)T * INP * B];       // [t][i][b]
__device__ float g_Hst[(size_t)(T + 1) * H * B];    // [t][h][b], t=0 stays zero (BSS)
__device__ float g_M[4 * H * H];                    // merged recurrent matrix
__device__ float g_C[G3 * B];                       // constants t>=1
__device__ float g_C0[G3 * B];                      // constants t==0
__device__ unsigned g_flags[NC];                    // barrier flags (monotonic)

__device__ __forceinline__ u64 pack2(float x, float y) {
    u64 r; asm("mov.b64 %0,{%1,%2};" : "=l"(r) : "f"(x), "f"(y)); return r;
}
__device__ __forceinline__ void unpack2(u64 v, float& x, float& y) {
    asm("mov.b64 {%0,%1},%2;" : "=f"(x), "=f"(y) : "l"(v));
}
__device__ __forceinline__ u64 fma2(u64 a, u64 b, u64 c) {
    u64 d; asm("fma.rn.f32x2 %0,%1,%2,%3;" : "=l"(d) : "l"(a), "l"(b), "l"(c)); return d;
}
__device__ __forceinline__ u64 add2(u64 a, u64 b) {
    u64 d; asm("add.rn.f32x2 %0,%1,%2;" : "=l"(d) : "l"(a), "l"(b)); return d;
}
__device__ __forceinline__ float sigf(float x) {
    return __fdividef(1.0f, 1.0f + __expf(-x));
}
__device__ __forceinline__ float tanhx(float x) {
    return __fdividef(2.0f, 1.0f + __expf(-2.0f * x)) - 1.0f;
}
// gpu-scope release store / acquire load (no MEMBAR, no L1 flush)
__device__ __forceinline__ void st_release(unsigned* p, unsigned v) {
    asm volatile("st.global.release.gpu.b32 [%0], %1;" :: "l"(p), "r"(v) : "memory");
}
__device__ __forceinline__ unsigned ld_acquire(const unsigned* p) {
    unsigned v;
    asm volatile("ld.global.acquire.gpu.b32 %0, [%1];" : "=r"(v) : "l"(p) : "memory");
    return v;
}

// ---------------------------------------------------------------------------
// obs (B,T,INP) -> obsT [t][i][b]
__global__ void k_transpose(const float* __restrict__ obs) {
    int t = blockIdx.x, b = threadIdx.x;
    const float4* src = (const float4*)(obs + (size_t)b * T * INP + (size_t)t * INP);
    float4 v[8];
#pragma unroll
    for (int q = 0; q < 8; q++) v[q] = src[q];
    float* dst = g_obsT + (size_t)t * (INP * B) + b;
#pragma unroll
    for (int q = 0; q < 8; q++) {
        dst[(4 * q + 0) * B] = v[q].x;
        dst[(4 * q + 1) * B] = v[q].y;
        dst[(4 * q + 2) * B] = v[q].z;
        dst[(4 * q + 3) * B] = v[q].w;
    }
}

// ---------------------------------------------------------------------------
// Merged recurrent matrix M (1024 x 256):
//  rows [0,512): W_hh + W_comb (r,z) ; [512,768): W_comb (xn) ; [768,1024): W_hh_n
//  W_comb[j,k] = sum_o W_ih[j, 32+o] * W_out[o, k]
__global__ void k_prep_M(const float* __restrict__ W_ih,
                         const float* __restrict__ W_hh,
                         const float* __restrict__ W_out) {
    int j = blockIdx.x, k = threadIdx.x;
    float v;
    if (j < 768) {
        float comb = 0.f;
#pragma unroll
        for (int o = 0; o < 32; o++)
            comb = fmaf(W_ih[j * 96 + 32 + o], W_out[o * H + k], comb);
        v = (j < 512) ? (W_hh[j * H + k] + comb) : comb;
    } else {
        v = W_hh[(j - 256) * H + k];
    }
    g_M[j * H + k] = v;
}

// ---------------------------------------------------------------------------
// Per-(gate-row, batch) constants.
__global__ void k_prep_C(const float* __restrict__ z_dyn,
                         const float* __restrict__ init_y,
                         const float* __restrict__ W_ih,
                         const float* __restrict__ b_ih,
                         const float* __restrict__ b_hh,
                         const float* __restrict__ b_out) {
    int j = blockIdx.x, b = threadIdx.x;
    float zp = 0.f, yb = 0.f, iy = 0.f;
#pragma unroll
    for (int i = 0; i < 32; i++)
        zp = fmaf(z_dyn[b * 32 + i], W_ih[j * 96 + 64 + i], zp);
#pragma unroll
    for (int o = 0; o < 32; o++) {
        float wy = W_ih[j * 96 + 32 + o];
        yb = fmaf(b_out[o], wy, yb);
        iy = fmaf(init_y[b * 32 + o], wy, iy);
    }
    float base = b_ih[j] + (j < 512 ? b_hh[j] : 0.f);
    g_C[j * B + b]  = zp + base + yb;
    g_C0[j * B + b] = zp + base + iy;
}

// ---------------------------------------------------------------------------
// Persistent sequential GRU loop, K-split.
// CTA c: h-cols [8*(c>>2), +8), batches [(c&3)*64, +64).
// Thread: kh = tid>>8 (K half), r = tid&255, s = r>>6 (pair), b = bg*64 + (r&63).
// kh=0 sums k in [0,128) + obs + constants; kh=1 sums k in [128,256).
// SMEM reduction combines halves; kh=0 computes gates and stores h.
__global__ void __launch_bounds__(THR, 1)
k_rnn(const float* __restrict__ W_ih, const float* __restrict__ b_hh) {
    __shared__ __align__(16) u64 m_s[256][4][4];    // [k][s][gate]      32KB
    __shared__ __align__(16) u64 c_s[3][256];       //                    6KB
    __shared__ __align__(16) u64 c0_s[3][256];      //                    6KB
    __shared__ __align__(16) u64 wobs_s[32][4][4];  // [i][s][gate+pad]   4KB
    __shared__ __align__(16) u64 red_s[256][4];     // reduction buffer   8KB

    const int tid = threadIdx.x;
    const int cta = blockIdx.x;
    const int g4  = cta >> 2;
    const int bg  = cta & 3;
    const int hcb = g4 * 8;
    const int kh  = tid >> 8;          // K half (warp-uniform)
    const int r   = tid & 255;
    const int s   = r >> 6;
    const int b   = bg * 64 + (r & 63);
    const int k0  = kh * 128;

    // M slice: each half loads 8 of the 16 (s2,g) planes, coalesced over k
    {
        int k = tid & 255;
#pragma unroll
        for (int e = 0; e < 8; e++) {
            int sg = kh * 8 + e;
            int s2 = sg >> 2, g = sg & 3;
            int r0 = (g * H + hcb + 2 * s2) * H + k;
            m_s[k][s2][g] = pack2(g_M[r0], g_M[r0 + H]);
        }
    }
    if (kh == 0) {
#pragma unroll
        for (int g = 0; g < 3; g++) {
            int rr = g * H + hcb + 2 * s;
            c_s [g][r] = pack2(g_C [rr * B + b], g_C [(rr + 1) * B + b]);
            c0_s[g][r] = pack2(g_C0[rr * B + b], g_C0[(rr + 1) * B + b]);
        }
    }
    if (tid < 32) {
#pragma unroll
        for (int s2 = 0; s2 < 4; s2++)
#pragma unroll
            for (int g = 0; g < 3; g++) {
                int rr = (g * H + hcb + 2 * s2) * 96 + tid;
                wobs_s[tid][s2][g] = pack2(W_ih[rr], W_ih[rr + 96]);
            }
    }
    const u64 bhh2 = pack2(b_hh[2 * H + hcb + 2 * s], b_hh[2 * H + hcb + 2 * s + 1]);
    __syncthreads();

    const unsigned base = ld_acquire(&g_flags[cta]);

    float hp0 = 0.f, hp1 = 0.f;

    for (int t = 0; t < T; t++) {
        u64 aR, aZ, aN, aH;

        const float* hs = g_Hst + (size_t)t * (H * B) + b + (size_t)k0 * B;
        float hb[4][8];

        if (kh == 0) {
            const u64* cs = (t == 0) ? &c0_s[0][0] : &c_s[0][0];
            aR = cs[0 * 256 + r];
            aZ = cs[1 * 256 + r];
            aN = cs[2 * 256 + r];
            aH = bhh2;

            // obs loads then h prefetch, covered by obs fma phase
            const float* op = g_obsT + (size_t)t * (INP * B) + b;
            float ov[32];
#pragma unroll
            for (int i = 0; i < 32; i++) ov[i] = op[i * B];
#pragma unroll
            for (int blk = 0; blk < 3; blk++)
#pragma unroll
                for (int q = 0; q < 8; q++)
                    hb[blk][q] = __ldcg(hs + (blk * 8 + q) * B);
#pragma unroll
            for (int i = 0; i < 32; i++) {
                u64 o2 = pack2(ov[i], ov[i]);
                ulonglong2 w01 = *(const ulonglong2*)&wobs_s[i][s][0];
                u64 w2v = wobs_s[i][s][2];
                aR = fma2(o2, w01.x, aR);
                aZ = fma2(o2, w01.y, aZ);
                aN = fma2(o2, w2v, aN);
            }
        } else {
            aR = 0; aZ = 0; aN = 0; aH = 0;
#pragma unroll
            for (int blk = 0; blk < 3; blk++)
#pragma unroll
                for (int q = 0; q < 8; q++)
                    hb[blk][q] = __ldcg(hs + (blk * 8 + q) * B);
        }

        // recurrent GEMM over this thread's K half (16 blocks of 8)
#pragma unroll 4
        for (int j = 0; j < 16; j++) {
#pragma unroll
            for (int q = 0; q < 8; q++) {
                int k = k0 + j * 8 + q;
                float hv = hb[j & 3][q];
                u64 h2 = pack2(hv, hv);
                ulonglong2 m01 = *(const ulonglong2*)&m_s[k][s][0];
                ulonglong2 m23 = *(const ulonglong2*)&m_s[k][s][2];
                aR = fma2(h2, m01.x, aR);
                aZ = fma2(h2, m01.y, aZ);
                aN = fma2(h2, m23.x, aN);
                aH = fma2(h2, m23.y, aH);
            }
            if (j < 13) {
#pragma unroll
                for (int q = 0; q < 8; q++)
                    hb[(j + 3) & 3][q] = __ldcg(hs + ((j + 3) * 8 + q) * B);
            }
        }

        // cross-half reduction
        if (kh == 1) {
            red_s[r][0] = aR; red_s[r][1] = aZ;
            red_s[r][2] = aN; red_s[r][3] = aH;
        }
        __syncthreads();

        if (kh == 0) {
            ulonglong2 p01 = *(const ulonglong2*)&red_s[r][0];
            ulonglong2 p23 = *(const ulonglong2*)&red_s[r][2];
            aR = add2(aR, p01.x);
            aZ = add2(aZ, p01.y);
            aN = add2(aN, p23.x);
            aH = add2(aH, p23.y);

            float xr0, xr1, xz0, xz1, xn0, xn1, hn0, hn1;
            unpack2(aR, xr0, xr1); unpack2(aZ, xz0, xz1);
            unpack2(aN, xn0, xn1); unpack2(aH, hn0, hn1);
            float r0 = sigf(xr0), r1 = sigf(xr1);
            float z0 = sigf(xz0), z1 = sigf(xz1);
            float n0 = tanhx(fmaf(r0, hn0, xn0));
            float n1 = tanhx(fmaf(r1, hn1, xn1));
            float h0 = fmaf(z0, hp0 - n0, n0);
            float h1 = fmaf(z1, hp1 - n1, n1);
            hp0 = h0; hp1 = h1;

            float* hd = g_Hst + (size_t)(t + 1) * (H * B);
            hd[(hcb + 2 * s) * B + b]     = h0;
            hd[(hcb + 2 * s + 1) * B + b] = h1;
        }

        // ---- release/acquire barrier over the 32 CTAs of this batch group ----
        __syncthreads();                      // h stores happen-before release
        const unsigned tgt = base + (unsigned)(t + 1);
        if (tid == 0) st_release(&g_flags[cta], tgt);
        if (tid < 32) {
            const unsigned* f = &g_flags[(tid << 2) | bg];
            while ((int)(ld_acquire(f) - tgt) < 0) { }
        }
        __syncthreads();
    }
}

// ---------------------------------------------------------------------------
// y[b,t,:] = h_t @ W_out^T + b_out
__global__ void __launch_bounds__(256)
k_out(const float* __restrict__ W_out, const float* __restrict__ b_out,
      float* __restrict__ out) {
    __shared__ u64 w2[16][H];
    int t = blockIdx.x, b = threadIdx.x;
#pragma unroll
    for (int p = 0; p < 16; p++)
        w2[p][b] = pack2(W_out[(2 * p) * H + b], W_out[(2 * p + 1) * H + b]);
    __syncthreads();

    u64 acc[16];
#pragma unroll
    for (int p = 0; p < 16; p++) acc[p] = pack2(b_out[2 * p], b_out[2 * p + 1]);

    const float* hs = g_Hst + (size_t)(t + 1) * (H * B) + b;
#pragma unroll 4
    for (int h = 0; h < H; h++) {
        float hv = __ldcg(hs + h * B);
        u64 hv2 = pack2(hv, hv);
#pragma unroll
        for (int p = 0; p < 16; p++) acc[p] = fma2(hv2, w2[p][h], acc[p]);
    }
    float* o = out + (size_t)b * (T * OUTD) + (size_t)t * OUTD;
#pragma unroll
    for (int p = 0; p < 16; p++) {
        float x, y; unpack2(acc[p], x, y);
        o[2 * p] = x; o[2 * p + 1] = y;
    }
}

// ---------------------------------------------------------------------------
extern "C" void kernel_launch(void* const* d_in, const int* in_sizes, int n_in,
                              void* d_out, int out_size) {
    const float* init_y = (const float*)d_in[0];
    const float* obs    = (const float*)d_in[1];
    const float* z_dyn  = (const float*)d_in[2];
    const float* W_ih   = (const float*)d_in[3];
    const float* W_hh   = (const float*)d_in[4];
    const float* b_ih   = (const float*)d_in[5];
    const float* b_hh   = (const float*)d_in[6];
    const float* W_out  = (const float*)d_in[7];
    const float* b_out  = (const float*)d_in[8];
    float* out = (float*)d_out;

    k_transpose<<<T, B>>>(obs);
    k_prep_M<<<1024, H>>>(W_ih, W_hh, W_out);
    k_prep_C<<<G3, B>>>(z_dyn, init_y, W_ih, b_ih, b_hh, b_out);
    k_rnn<<<NC, THR>>>(W_ih, b_hh);
    k_out<<<T, B>>>(W_out, b_out, out);
}